// round 1
// baseline (speedup 1.0000x reference)
#include <cuda_runtime.h>

#define NN   65536
#define CCH  128
#define KP   64
#define EE   2097152
#define BB   64
#define NPER 1024

#define N1 (BB*KP*CCH)      /* 524288  x_out            */
#define N2 (2*BB*KP*KP)     /* 524288  edge_index_out   */
#define N3 (BB*KP)          /* 4096    batch_out        */

// ---- scratch (device globals; no runtime allocation) ----
__device__ float g_m  [NN*KP];   // elu(x @ W_msg)
__device__ float g_r  [NN*KP];   // x @ W_root + b
__device__ float g_agg[NN*KP];   // segment_sum(m[src], dst)
__device__ float g_S  [NN*KP];   // softmax(tanh(agg + r))
__device__ float g_out[N1];      // pooled output before copy to d_out

// ---------------------------------------------------------------- zeroing
__global__ void k_zero_agg() {
    int i = blockIdx.x * blockDim.x + threadIdx.x;   // exactly NN*KP/4 threads
    ((float4*)g_agg)[i] = make_float4(0.f, 0.f, 0.f, 0.f);
}
__global__ void k_zero_out() {
    int i = blockIdx.x * blockDim.x + threadIdx.x;   // exactly N1/4 threads
    ((float4*)g_out)[i] = make_float4(0.f, 0.f, 0.f, 0.f);
}

// ---------------------------------------------------------------- K1: fused input GEMM
// Per block: 64 rows of x, full concat weight [C x 128] (W_msg | W_root) in SMEM.
// Thread tile 4 rows x 8 outputs.  Epilogue applies elu (msg half) or +b (root half).
__global__ void k1_gemm(const float* __restrict__ x, const float* __restrict__ Wm,
                        const float* __restrict__ Wr, const float* __restrict__ bv) {
    extern __shared__ float sm1[];
    float* Wc = sm1;               // 128*128 floats = 64KB
    float* xs = sm1 + CCH * 128;   // 64*128  floats = 32KB
    int t = threadIdx.x;           // 256 threads
    int row0 = blockIdx.x * 64;

    for (int i = t; i < CCH * 128; i += 256) {
        int c = i >> 7, j = i & 127;
        Wc[i] = (j < KP) ? Wm[c * KP + j] : Wr[c * KP + (j - KP)];
    }
    const float4* xg = (const float4*)(x + (size_t)row0 * CCH);
    float4* xs4 = (float4*)xs;
    for (int i = t; i < 64 * CCH / 4; i += 256) xs4[i] = xg[i];
    __syncthreads();

    int r0 = (t >> 4) * 4;
    int j0 = (t & 15) * 8;
    float acc[4][8];
    #pragma unroll
    for (int i = 0; i < 4; i++)
        #pragma unroll
        for (int j = 0; j < 8; j++) acc[i][j] = 0.f;

    #pragma unroll 8
    for (int c = 0; c < CCH; c++) {
        float xv[4];
        #pragma unroll
        for (int i = 0; i < 4; i++) xv[i] = xs[(r0 + i) * CCH + c];
        float4 w0 = *(const float4*)&Wc[c * 128 + j0];
        float4 w1 = *(const float4*)&Wc[c * 128 + j0 + 4];
        float wv[8] = {w0.x, w0.y, w0.z, w0.w, w1.x, w1.y, w1.z, w1.w};
        #pragma unroll
        for (int i = 0; i < 4; i++)
            #pragma unroll
            for (int j = 0; j < 8; j++)
                acc[i][j] = fmaf(xv[i], wv[j], acc[i][j]);
    }

    if (j0 < KP) {
        // message half: elu
        #pragma unroll
        for (int i = 0; i < 4; i++) {
            float o[8];
            #pragma unroll
            for (int j = 0; j < 8; j++) {
                float v = acc[i][j];
                o[j] = (v > 0.f) ? v : expm1f(v);
            }
            float* p = g_m + (size_t)(row0 + r0 + i) * KP + j0;
            *(float4*)p       = make_float4(o[0], o[1], o[2], o[3]);
            *(float4*)(p + 4) = make_float4(o[4], o[5], o[6], o[7]);
        }
    } else {
        int jj = j0 - KP;
        float bb[8];
        #pragma unroll
        for (int j = 0; j < 8; j++) bb[j] = __ldg(&bv[jj + j]);
        #pragma unroll
        for (int i = 0; i < 4; i++) {
            float* p = g_r + (size_t)(row0 + r0 + i) * KP + jj;
            *(float4*)p       = make_float4(acc[i][0]+bb[0], acc[i][1]+bb[1], acc[i][2]+bb[2], acc[i][3]+bb[3]);
            *(float4*)(p + 4) = make_float4(acc[i][4]+bb[4], acc[i][5]+bb[5], acc[i][6]+bb[6], acc[i][7]+bb[7]);
        }
    }
}

// ---------------------------------------------------------------- K2: edge scatter
// 16 threads per edge, each handles a float4 slice; vectorized L2 reduction.
__global__ void k2_scatter(const int* __restrict__ ei) {
    int gid = blockIdx.x * blockDim.x + threadIdx.x;  // exactly EE*16 threads
    int e   = gid >> 4;
    int seg = gid & 15;
    int src = __ldg(&ei[e]);
    int dst = __ldg(&ei[EE + e]);
    float4 v = ((const float4*)g_m)[(size_t)src * 16 + seg];
    float* p = g_agg + (size_t)dst * KP + seg * 4;
    asm volatile("red.global.add.v4.f32 [%0], {%1,%2,%3,%4};"
                 :: "l"(p), "f"(v.x), "f"(v.y), "f"(v.z), "f"(v.w) : "memory");
}

// ---------------------------------------------------------------- K3: tanh + softmax over K=64
// One warp per node, 2 values per lane.
__global__ void k3_softmax() {
    int idx  = blockIdx.x * blockDim.x + threadIdx.x;
    int n    = idx >> 5;
    int lane = idx & 31;
    float2 a = ((const float2*)g_agg)[(size_t)n * 32 + lane];
    float2 r = ((const float2*)g_r  )[(size_t)n * 32 + lane];
    float v0 = tanhf(a.x + r.x);
    float v1 = tanhf(a.y + r.y);
    float mx = fmaxf(v0, v1);
    #pragma unroll
    for (int o = 16; o > 0; o >>= 1) mx = fmaxf(mx, __shfl_xor_sync(0xffffffffu, mx, o));
    float e0 = expf(v0 - mx), e1 = expf(v1 - mx);
    float s = e0 + e1;
    #pragma unroll
    for (int o = 16; o > 0; o >>= 1) s += __shfl_xor_sync(0xffffffffu, s, o);
    float inv = 1.0f / s;
    ((float2*)g_S)[(size_t)n * 32 + lane] = make_float2(e0 * inv, e1 * inv);
}

// ---------------------------------------------------------------- K4: out[b,k,c] = sum_n S[b,n,k] * x[b,n,c]
// Grid (B, NPER/128). Each block: 128-n chunk, full 64x128 output tile, v4 red into g_out.
__global__ void k4_pool(const float* __restrict__ x) {
    extern __shared__ float sm4[];
    float* Ss = sm4;             // 128*64  = 32KB
    float* Xs = sm4 + 128 * KP;  // 128*128 = 64KB
    int b  = blockIdx.x;
    int n0 = blockIdx.y * 128;
    int t  = threadIdx.x;        // 256

    const float4* Sg = (const float4*)(g_S + ((size_t)b * NPER + n0) * KP);
    for (int i = t; i < 128 * KP / 4; i += 256) ((float4*)Ss)[i] = Sg[i];
    const float4* Xg = (const float4*)(x + ((size_t)b * NPER + n0) * CCH);
    for (int i = t; i < 128 * CCH / 4; i += 256) ((float4*)Xs)[i] = Xg[i];
    __syncthreads();

    int k0 = (t >> 4) * 4;
    int c0 = (t & 15) * 8;
    float acc[4][8];
    #pragma unroll
    for (int i = 0; i < 4; i++)
        #pragma unroll
        for (int j = 0; j < 8; j++) acc[i][j] = 0.f;

    #pragma unroll 4
    for (int n = 0; n < 128; n++) {
        float4 s4 = *(const float4*)&Ss[n * KP + k0];
        float sv[4] = {s4.x, s4.y, s4.z, s4.w};
        float4 x0 = *(const float4*)&Xs[n * CCH + c0];
        float4 x1 = *(const float4*)&Xs[n * CCH + c0 + 4];
        float xv[8] = {x0.x, x0.y, x0.z, x0.w, x1.x, x1.y, x1.z, x1.w};
        #pragma unroll
        for (int i = 0; i < 4; i++)
            #pragma unroll
            for (int j = 0; j < 8; j++)
                acc[i][j] = fmaf(sv[i], xv[j], acc[i][j]);
    }

    #pragma unroll
    for (int i = 0; i < 4; i++) {
        float* p = g_out + ((size_t)b * KP + k0 + i) * CCH + c0;
        asm volatile("red.global.add.v4.f32 [%0], {%1,%2,%3,%4};"
                     :: "l"(p), "f"(acc[i][0]), "f"(acc[i][1]), "f"(acc[i][2]), "f"(acc[i][3]) : "memory");
        asm volatile("red.global.add.v4.f32 [%0], {%1,%2,%3,%4};"
                     :: "l"(p + 4), "f"(acc[i][4]), "f"(acc[i][5]), "f"(acc[i][6]), "f"(acc[i][7]) : "memory");
    }
}

// ---------------------------------------------------------------- output assembly
__global__ void k_copy_out(float* __restrict__ out, int out_size) {
    int gid = blockIdx.x * blockDim.x + threadIdx.x;
    if (gid < N1 && gid < out_size) out[gid] = g_out[gid];
}

// edge_index_out / batch_out are pure index patterns (only written when the
// harness's out buffer is large enough to hold the concatenated tuple).
__global__ void k_extras(float* __restrict__ out, int out_size) {
    int gid = blockIdx.x * blockDim.x + threadIdx.x;
    if (gid < N2 && out_size >= N1 + N2) {
        int r   = gid / (BB * KP * KP);
        int rem = gid - r * (BB * KP * KP);
        int b   = rem >> 12;       // / (K*K) = /4096
        int ij  = rem & 4095;
        int i   = ij >> 6, j = ij & 63;
        out[N1 + gid] = (float)(b * KP + (r == 0 ? i : j));
    }
    if (gid < N3 && out_size >= N1 + N2 + N3) {
        out[N1 + N2 + gid] = (float)(gid >> 6);   // batch_out[b*K+k] = b
    }
}

// ---------------------------------------------------------------- launch
extern "C" void kernel_launch(void* const* d_in, const int* in_sizes, int n_in,
                              void* d_out, int out_size) {
    const float* x  = (const float*)d_in[0];
    const int*   ei = (const int*)  d_in[1];
    // d_in[2] = batch (unused; equal-size graphs)
    const float* Wm = (const float*)d_in[3];
    const float* Wr = (const float*)d_in[4];
    const float* bv = (const float*)d_in[5];
    float* out = (float*)d_out;

    cudaFuncSetAttribute(k1_gemm, cudaFuncAttributeMaxDynamicSharedMemorySize, 98304);
    cudaFuncSetAttribute(k4_pool, cudaFuncAttributeMaxDynamicSharedMemorySize, 98304);

    k_zero_agg<<<2048, 512>>>();                       // NN*KP/4 = 1M float4
    k_zero_out<<<256, 512>>>();                        // N1/4 float4
    k1_gemm<<<NN / 64, 256, 98304>>>(x, Wm, Wr, bv);
    k2_scatter<<<(EE * 16) / 256, 256>>>(ei);
    k3_softmax<<<NN / 8, 256>>>();
    k4_pool<<<dim3(BB, NPER / 128), 256, 98304>>>(x);
    k_copy_out<<<(N1 + 255) / 256, 256>>>(out, out_size);
    if (out_size >= N1 + N2) k_extras<<<(N2 + 255) / 256, 256>>>(out, out_size);
}

// round 2
// speedup vs baseline: 1.0850x; 1.0850x over previous
#include <cuda_runtime.h>

#define NN   65536
#define CCH  128
#define KP   64
#define EE   2097152
#define BB   64
#define NPER 1024
#define EPG  (EE/BB)        /* 32768 edges per graph (edge list is graph-blocked) */

#define N1 (BB*KP*CCH)      /* 524288  x_out            */
#define N2 (2*BB*KP*KP)     /* 524288  edge_index_out   */
#define N3 (BB*KP)          /* 4096    batch_out        */

// ---- scratch (device globals; no runtime allocation) ----
__device__ float g_m  [NN*KP];   // elu(x @ W_msg)
__device__ float g_r  [NN*KP];   // x @ W_root + b
__device__ float g_S  [NN*KP];   // softmax(tanh(agg + r))
__device__ int   g_cnt[NN];      // in-degree per node
__device__ int   g_ofs[NN];      // CSR fill cursor (start, becomes end after fill)
__device__ int   g_ebin[EE];     // src ids binned by dst

// ---------------------------------------------------------------- zeroing
__global__ void k_zero_out(float* __restrict__ out) {
    int i = blockIdx.x * blockDim.x + threadIdx.x;   // exactly N1/4 threads
    ((float4*)out)[i] = make_float4(0.f, 0.f, 0.f, 0.f);
}
__global__ void k_zero_cnt() {
    int i = blockIdx.x * blockDim.x + threadIdx.x;   // exactly NN/4 threads
    ((int4*)g_cnt)[i] = make_int4(0, 0, 0, 0);
}

// ---------------------------------------------------------------- K1: fused input GEMM
// Per block: 64 rows of x, full concat weight [C x 128] (W_msg | W_root) in SMEM.
// Thread tile 4 rows x 8 outputs.  Epilogue applies elu (msg half) or +b (root half).
__global__ void k1_gemm(const float* __restrict__ x, const float* __restrict__ Wm,
                        const float* __restrict__ Wr, const float* __restrict__ bv) {
    extern __shared__ float sm1[];
    float* Wc = sm1;               // 128*128 floats = 64KB
    float* xs = sm1 + CCH * 128;   // 64*128  floats = 32KB
    int t = threadIdx.x;           // 256 threads
    int row0 = blockIdx.x * 64;

    for (int i = t; i < CCH * 128; i += 256) {
        int c = i >> 7, j = i & 127;
        Wc[i] = (j < KP) ? Wm[c * KP + j] : Wr[c * KP + (j - KP)];
    }
    const float4* xg = (const float4*)(x + (size_t)row0 * CCH);
    float4* xs4 = (float4*)xs;
    for (int i = t; i < 64 * CCH / 4; i += 256) xs4[i] = xg[i];
    __syncthreads();

    int r0 = (t >> 4) * 4;
    int j0 = (t & 15) * 8;
    float acc[4][8];
    #pragma unroll
    for (int i = 0; i < 4; i++)
        #pragma unroll
        for (int j = 0; j < 8; j++) acc[i][j] = 0.f;

    #pragma unroll 8
    for (int c = 0; c < CCH; c++) {
        float xv[4];
        #pragma unroll
        for (int i = 0; i < 4; i++) xv[i] = xs[(r0 + i) * CCH + c];
        float4 w0 = *(const float4*)&Wc[c * 128 + j0];
        float4 w1 = *(const float4*)&Wc[c * 128 + j0 + 4];
        float wv[8] = {w0.x, w0.y, w0.z, w0.w, w1.x, w1.y, w1.z, w1.w};
        #pragma unroll
        for (int i = 0; i < 4; i++)
            #pragma unroll
            for (int j = 0; j < 8; j++)
                acc[i][j] = fmaf(xv[i], wv[j], acc[i][j]);
    }

    if (j0 < KP) {
        // message half: elu
        #pragma unroll
        for (int i = 0; i < 4; i++) {
            float o[8];
            #pragma unroll
            for (int j = 0; j < 8; j++) {
                float v = acc[i][j];
                o[j] = (v > 0.f) ? v : expm1f(v);
            }
            float* p = g_m + (size_t)(row0 + r0 + i) * KP + j0;
            *(float4*)p       = make_float4(o[0], o[1], o[2], o[3]);
            *(float4*)(p + 4) = make_float4(o[4], o[5], o[6], o[7]);
        }
    } else {
        int jj = j0 - KP;
        float bb[8];
        #pragma unroll
        for (int j = 0; j < 8; j++) bb[j] = __ldg(&bv[jj + j]);
        #pragma unroll
        for (int i = 0; i < 4; i++) {
            float* p = g_r + (size_t)(row0 + r0 + i) * KP + jj;
            *(float4*)p       = make_float4(acc[i][0]+bb[0], acc[i][1]+bb[1], acc[i][2]+bb[2], acc[i][3]+bb[3]);
            *(float4*)(p + 4) = make_float4(acc[i][4]+bb[4], acc[i][5]+bb[5], acc[i][6]+bb[6], acc[i][7]+bb[7]);
        }
    }
}

// ---------------------------------------------------------------- K2a: in-degree histogram
__global__ void k_count(const int* __restrict__ ei) {
    int e = blockIdx.x * blockDim.x + threadIdx.x;   // exactly EE threads
    atomicAdd(&g_cnt[__ldg(&ei[EE + e])], 1);        // no return -> RED
}

// ---------------------------------------------------------------- K2b: per-graph exclusive scan
// Edges are graph-blocked: graph g's bin occupies [g*EPG, (g+1)*EPG).
__global__ void k_scan() {
    __shared__ int sd[NPER];
    int g = blockIdx.x, t = threadIdx.x;             // BB blocks x 1024 threads
    int c = g_cnt[g * NPER + t];
    sd[t] = c;
    __syncthreads();
    #pragma unroll
    for (int off = 1; off < NPER; off <<= 1) {
        int u = (t >= off) ? sd[t - off] : 0;
        __syncthreads();
        sd[t] += u;
        __syncthreads();
    }
    g_ofs[g * NPER + t] = g * EPG + sd[t] - c;       // exclusive prefix + graph base
}

// ---------------------------------------------------------------- K2c: bin fill
__global__ void k_fill(const int* __restrict__ ei) {
    int e = blockIdx.x * blockDim.x + threadIdx.x;   // exactly EE threads
    int src = __ldg(&ei[e]);
    int dst = __ldg(&ei[EE + e]);
    int pos = atomicAdd(&g_ofs[dst], 1);
    g_ebin[pos] = src;
}

// ---------------------------------------------------------------- K2d: SpMM + tanh + softmax (fused)
// One warp per dst node: register accumulation (2 floats/lane), no atomics.
__global__ void k_spmm() {
    int wid  = (blockIdx.x * blockDim.x + threadIdx.x) >> 5;  // node id, exactly NN warps
    int lane = threadIdx.x & 31;
    int end  = g_ofs[wid];           // after fill: start + deg
    int cn   = g_cnt[wid];
    int start = end - cn;

    float a0 = 0.f, a1 = 0.f;
    for (int i0 = start; i0 < end; i0 += 32) {
        int rem = end - i0;
        int s = 0;
        if (lane < rem) s = g_ebin[i0 + lane];
        int mcnt = rem < 32 ? rem : 32;
        for (int j = 0; j < mcnt; j++) {
            int sj = __shfl_sync(0xffffffffu, s, j);
            float2 v = ((const float2*)g_m)[(size_t)sj * 32 + lane];
            a0 += v.x;
            a1 += v.y;
        }
    }

    float2 r = ((const float2*)g_r)[(size_t)wid * 32 + lane];
    float v0 = tanhf(a0 + r.x);
    float v1 = tanhf(a1 + r.y);
    float mx = fmaxf(v0, v1);
    #pragma unroll
    for (int o = 16; o > 0; o >>= 1) mx = fmaxf(mx, __shfl_xor_sync(0xffffffffu, mx, o));
    float e0 = expf(v0 - mx), e1 = expf(v1 - mx);
    float s = e0 + e1;
    #pragma unroll
    for (int o = 16; o > 0; o >>= 1) s += __shfl_xor_sync(0xffffffffu, s, o);
    float inv = 1.0f / s;
    ((float2*)g_S)[(size_t)wid * 32 + lane] = make_float2(e0 * inv, e1 * inv);
}

// ---------------------------------------------------------------- K4: out[b,k,c] = sum_n S[b,n,k] * x[b,n,c]
// Grid (B, NPER/128). Reduces directly into d_out (pre-zeroed).
__global__ void k4_pool(const float* __restrict__ x, float* __restrict__ out) {
    extern __shared__ float sm4[];
    float* Ss = sm4;             // 128*64  = 32KB
    float* Xs = sm4 + 128 * KP;  // 128*128 = 64KB
    int b  = blockIdx.x;
    int n0 = blockIdx.y * 128;
    int t  = threadIdx.x;        // 256

    const float4* Sg = (const float4*)(g_S + ((size_t)b * NPER + n0) * KP);
    for (int i = t; i < 128 * KP / 4; i += 256) ((float4*)Ss)[i] = Sg[i];
    const float4* Xg = (const float4*)(x + ((size_t)b * NPER + n0) * CCH);
    for (int i = t; i < 128 * CCH / 4; i += 256) ((float4*)Xs)[i] = Xg[i];
    __syncthreads();

    int k0 = (t >> 4) * 4;
    int c0 = (t & 15) * 8;
    float acc[4][8];
    #pragma unroll
    for (int i = 0; i < 4; i++)
        #pragma unroll
        for (int j = 0; j < 8; j++) acc[i][j] = 0.f;

    #pragma unroll 4
    for (int n = 0; n < 128; n++) {
        float4 s4 = *(const float4*)&Ss[n * KP + k0];
        float sv[4] = {s4.x, s4.y, s4.z, s4.w};
        float4 x0 = *(const float4*)&Xs[n * CCH + c0];
        float4 x1 = *(const float4*)&Xs[n * CCH + c0 + 4];
        float xv[8] = {x0.x, x0.y, x0.z, x0.w, x1.x, x1.y, x1.z, x1.w};
        #pragma unroll
        for (int i = 0; i < 4; i++)
            #pragma unroll
            for (int j = 0; j < 8; j++)
                acc[i][j] = fmaf(sv[i], xv[j], acc[i][j]);
    }

    #pragma unroll
    for (int i = 0; i < 4; i++) {
        float* p = out + ((size_t)b * KP + k0 + i) * CCH + c0;
        asm volatile("red.global.add.v4.f32 [%0], {%1,%2,%3,%4};"
                     :: "l"(p), "f"(acc[i][0]), "f"(acc[i][1]), "f"(acc[i][2]), "f"(acc[i][3]) : "memory");
        asm volatile("red.global.add.v4.f32 [%0], {%1,%2,%3,%4};"
                     :: "l"(p + 4), "f"(acc[i][4]), "f"(acc[i][5]), "f"(acc[i][6]), "f"(acc[i][7]) : "memory");
    }
}

// ---------------------------------------------------------------- extras
// edge_index_out / batch_out are pure index patterns (only written when the
// harness's out buffer is large enough to hold the concatenated tuple).
__global__ void k_extras(float* __restrict__ out, int out_size) {
    int gid = blockIdx.x * blockDim.x + threadIdx.x;
    if (gid < N2 && out_size >= N1 + N2) {
        int r   = gid / (BB * KP * KP);
        int rem = gid - r * (BB * KP * KP);
        int b   = rem >> 12;       // / (K*K) = /4096
        int ij  = rem & 4095;
        int i   = ij >> 6, j = ij & 63;
        out[N1 + gid] = (float)(b * KP + (r == 0 ? i : j));
    }
    if (gid < N3 && out_size >= N1 + N2 + N3) {
        out[N1 + N2 + gid] = (float)(gid >> 6);   // batch_out[b*K+k] = b
    }
}

// ---------------------------------------------------------------- launch
extern "C" void kernel_launch(void* const* d_in, const int* in_sizes, int n_in,
                              void* d_out, int out_size) {
    const float* x  = (const float*)d_in[0];
    const int*   ei = (const int*)  d_in[1];
    // d_in[2] = batch (unused; equal-size graphs)
    const float* Wm = (const float*)d_in[3];
    const float* Wr = (const float*)d_in[4];
    const float* bv = (const float*)d_in[5];
    float* out = (float*)d_out;

    cudaFuncSetAttribute(k1_gemm, cudaFuncAttributeMaxDynamicSharedMemorySize, 98304);
    cudaFuncSetAttribute(k4_pool, cudaFuncAttributeMaxDynamicSharedMemorySize, 98304);

    k_zero_out<<<256, 512>>>(out);                   // N1/4 float4
    k_zero_cnt<<<32, 512>>>();                       // NN/4 int4
    k1_gemm<<<NN / 64, 256, 98304>>>(x, Wm, Wr, bv);
    k_count<<<EE / 256, 256>>>(ei);
    k_scan<<<BB, NPER>>>();
    k_fill<<<EE / 256, 256>>>(ei);
    k_spmm<<<NN / 8, 256>>>();
    k4_pool<<<dim3(BB, NPER / 128), 256, 98304>>>(x, out);
    if (out_size >= N1 + N2) k_extras<<<(N2 + 255) / 256, 256>>>(out, out_size);
}

// round 3
// speedup vs baseline: 1.3613x; 1.2547x over previous
#include <cuda_runtime.h>

#define NN   65536
#define CCH  128
#define KP   64
#define EE   2097152
#define BB   64
#define NPER 1024
#define EPG  (EE/BB)        /* 32768 edges per graph (edge list is graph-blocked) */

#define N1 (BB*KP*CCH)      /* 524288  x_out            */
#define N2 (2*BB*KP*KP)     /* 524288  edge_index_out   */
#define N3 (BB*KP)          /* 4096    batch_out        */

// packed fp32x2 ops (Blackwell FFMA2 path — only reachable via PTX)
#define FMA_F32X2(d, a, b, c) \
    asm("fma.rn.f32x2 %0, %1, %2, %3;" : "=l"(d) : "l"(a), "l"(b), "l"(c))
#define ADD_F32X2(d, a, b) \
    asm("add.rn.f32x2 %0, %1, %2;" : "=l"(d) : "l"(a), "l"(b))
#define PACK_DUP(d, f) \
    asm("mov.b64 %0, {%1, %1};" : "=l"(d) : "f"(f))

typedef unsigned long long ull;
union F2U { ull u; float2 f; };

// ---- scratch (device globals; no runtime allocation) ----
__device__ float g_m  [NN*KP];   // elu(x @ W_msg)
__device__ float g_r  [NN*KP];   // x @ W_root + b
__device__ float g_S  [NN*KP];   // softmax(tanh(agg + r))
__device__ int   g_cnt[NN];      // in-degree per node
__device__ int   g_ofs[NN];      // CSR fill cursor (start, becomes end after fill)
__device__ int   g_ebin[EE];     // src ids binned by dst

// ---------------------------------------------------------------- init: zero d_out + counters
__global__ void k_init(float* __restrict__ out) {
    int i = blockIdx.x * blockDim.x + threadIdx.x;   // 288*512 = 147456 threads
    if (i < N1/4) ((float4*)out)[i] = make_float4(0.f, 0.f, 0.f, 0.f);
    else {
        int j = i - N1/4;
        if (j < NN/4) ((int4*)g_cnt)[j] = make_int4(0, 0, 0, 0);
    }
}

// ---------------------------------------------------------------- K1: fused input GEMM (f32x2)
// 512 threads, tile 128 rows x 128 cols, full K=C=128.
// SMEM: W concat [c][j] 64KB + x transposed XT[c][row] 64KB.
// Thread tile: 8 rows (4 row-pairs, packed) x 4 cols. Epilogue: elu / +b.
__global__ void k1_gemm(const float* __restrict__ x, const float* __restrict__ Wm,
                        const float* __restrict__ Wr, const float* __restrict__ bv) {
    extern __shared__ float sm1[];
    float* Wc = sm1;               // [128][128]
    float* XT = sm1 + CCH * 128;   // [c][row] 128x128
    int t = threadIdx.x;           // 512
    int row0 = blockIdx.x * 128;

    // load W (coalesced, conflict-free)
    for (int i = t; i < CCH * 128; i += 512) {
        int c = i >> 7, j = i & 127;
        Wc[i] = (j < KP) ? Wm[c * KP + j] : Wr[c * KP + (j - KP)];
    }
    // load x transposed: thread -> (row, c8); 32B contiguous per thread; STS row-consecutive lanes
    {
        const float4* xg4 = (const float4*)(x + (size_t)row0 * CCH);
        for (int i = t; i < 128 * 16; i += 512) {
            int row = i & 127, c8 = i >> 7;
            float4 v0 = xg4[row * 32 + 2 * c8];
            float4 v1 = xg4[row * 32 + 2 * c8 + 1];
            int cb = 8 * c8;
            XT[(cb + 0) * 128 + row] = v0.x;
            XT[(cb + 1) * 128 + row] = v0.y;
            XT[(cb + 2) * 128 + row] = v0.z;
            XT[(cb + 3) * 128 + row] = v0.w;
            XT[(cb + 4) * 128 + row] = v1.x;
            XT[(cb + 5) * 128 + row] = v1.y;
            XT[(cb + 6) * 128 + row] = v1.z;
            XT[(cb + 7) * 128 + row] = v1.w;
        }
    }
    __syncthreads();

    int r0 = (t >> 5) * 8;        // 16 groups -> 128 rows
    int j0 = (t & 31) * 4;        // 32 groups -> 128 cols
    ull acc[4][4];
    #pragma unroll
    for (int i = 0; i < 4; i++)
        #pragma unroll
        for (int j = 0; j < 4; j++) acc[i][j] = 0ull;

    #pragma unroll 4
    for (int c = 0; c < CCH; c++) {
        // x row-pairs: direct 8B shared loads (broadcast across warp)
        ull xp[4];
        #pragma unroll
        for (int i = 0; i < 4; i++)
            xp[i] = *(const ull*)&XT[c * 128 + r0 + 2 * i];
        // w: 4 scalars duplicated into both packed halves
        float4 w4 = *(const float4*)&Wc[c * 128 + j0];
        ull wd[4];
        PACK_DUP(wd[0], w4.x); PACK_DUP(wd[1], w4.y);
        PACK_DUP(wd[2], w4.z); PACK_DUP(wd[3], w4.w);
        #pragma unroll
        for (int i = 0; i < 4; i++)
            #pragma unroll
            for (int j = 0; j < 4; j++)
                FMA_F32X2(acc[i][j], xp[i], wd[j], acc[i][j]);
    }

    if (j0 < KP) {
        // message half: elu
        #pragma unroll
        for (int i = 0; i < 4; i++) {
            F2U a[4];
            #pragma unroll
            for (int j = 0; j < 4; j++) a[j].u = acc[i][j];
            #pragma unroll
            for (int h = 0; h < 2; h++) {
                int row = row0 + r0 + 2 * i + h;
                float o[4];
                #pragma unroll
                for (int j = 0; j < 4; j++) {
                    float v = h ? a[j].f.y : a[j].f.x;
                    o[j] = (v > 0.f) ? v : expm1f(v);
                }
                *(float4*)&g_m[(size_t)row * KP + j0] = make_float4(o[0], o[1], o[2], o[3]);
            }
        }
    } else {
        int jj = j0 - KP;
        float4 bb = *(const float4*)&bv[jj];
        #pragma unroll
        for (int i = 0; i < 4; i++) {
            F2U a[4];
            #pragma unroll
            for (int j = 0; j < 4; j++) a[j].u = acc[i][j];
            #pragma unroll
            for (int h = 0; h < 2; h++) {
                int row = row0 + r0 + 2 * i + h;
                float o0 = (h ? a[0].f.y : a[0].f.x) + bb.x;
                float o1 = (h ? a[1].f.y : a[1].f.x) + bb.y;
                float o2 = (h ? a[2].f.y : a[2].f.x) + bb.z;
                float o3 = (h ? a[3].f.y : a[3].f.x) + bb.w;
                *(float4*)&g_r[(size_t)row * KP + jj] = make_float4(o0, o1, o2, o3);
            }
        }
    }
}

// ---------------------------------------------------------------- K2a: in-degree histogram (SMEM)
// 256 blocks x 8192 edges; each block fully inside one graph -> dst & 1023 bins.
__global__ void k_count(const int* __restrict__ ei) {
    __shared__ int h[NPER];
    int t = threadIdx.x;                   // 512
    h[t] = 0; h[t + 512] = 0;
    __syncthreads();
    const int4* d4 = (const int4*)(ei + EE + blockIdx.x * 8192);
    #pragma unroll
    for (int i = 0; i < 4; i++) {
        int4 d = __ldg(&d4[i * 512 + t]);
        atomicAdd(&h[d.x & (NPER-1)], 1);
        atomicAdd(&h[d.y & (NPER-1)], 1);
        atomicAdd(&h[d.z & (NPER-1)], 1);
        atomicAdd(&h[d.w & (NPER-1)], 1);
    }
    __syncthreads();
    int base = (blockIdx.x >> 2) * NPER;   // 4 blocks per graph
    if (h[t])       atomicAdd(&g_cnt[base + t], h[t]);
    if (h[t + 512]) atomicAdd(&g_cnt[base + t + 512], h[t + 512]);
}

// ---------------------------------------------------------------- K2b: per-graph exclusive scan
__global__ void k_scan() {
    __shared__ int sd[NPER];
    int g = blockIdx.x, t = threadIdx.x;             // BB blocks x 1024 threads
    int c = g_cnt[g * NPER + t];
    sd[t] = c;
    __syncthreads();
    #pragma unroll
    for (int off = 1; off < NPER; off <<= 1) {
        int u = (t >= off) ? sd[t - off] : 0;
        __syncthreads();
        sd[t] += u;
        __syncthreads();
    }
    g_ofs[g * NPER + t] = g * EPG + sd[t] - c;       // exclusive prefix + graph base
}

// ---------------------------------------------------------------- K2c: bin fill
__global__ void k_fill(const int* __restrict__ ei) {
    int e = blockIdx.x * blockDim.x + threadIdx.x;   // exactly EE threads
    int src = __ldg(&ei[e]);
    int dst = __ldg(&ei[EE + e]);
    int pos = atomicAdd(&g_ofs[dst], 1);
    g_ebin[pos] = src;
}

// ---------------------------------------------------------------- K2d: SpMM + tanh + softmax (fused)
// One warp per dst node: register accumulation; 4-way unrolled gather for MLP.
__global__ void k_spmm() {
    int wid  = (blockIdx.x * blockDim.x + threadIdx.x) >> 5;  // node id
    int lane = threadIdx.x & 31;
    int end  = g_ofs[wid];           // after fill: start + deg
    int cn   = g_cnt[wid];
    int start = end - cn;
    const float2* m2 = (const float2*)g_m;

    ull acc = 0ull;
    int i0 = start;
    for (; i0 + 32 <= end; i0 += 32) {
        int s = g_ebin[i0 + lane];
        #pragma unroll
        for (int j = 0; j < 32; j += 4) {
            int s0 = __shfl_sync(0xffffffffu, s, j + 0);
            int s1 = __shfl_sync(0xffffffffu, s, j + 1);
            int s2 = __shfl_sync(0xffffffffu, s, j + 2);
            int s3 = __shfl_sync(0xffffffffu, s, j + 3);
            F2U v0, v1, v2, v3;
            v0.f = m2[(size_t)s0 * 32 + lane];
            v1.f = m2[(size_t)s1 * 32 + lane];
            v2.f = m2[(size_t)s2 * 32 + lane];
            v3.f = m2[(size_t)s3 * 32 + lane];
            ADD_F32X2(v0.u, v0.u, v1.u);
            ADD_F32X2(v2.u, v2.u, v3.u);
            ADD_F32X2(v0.u, v0.u, v2.u);
            ADD_F32X2(acc, acc, v0.u);
        }
    }
    int rem = end - i0;
    if (rem > 0) {
        int s = (lane < rem) ? g_ebin[i0 + lane] : 0;
        for (int j = 0; j < rem; j++) {
            int sj = __shfl_sync(0xffffffffu, s, j);
            F2U v; v.f = m2[(size_t)sj * 32 + lane];
            ADD_F32X2(acc, acc, v.u);
        }
    }

    F2U a; a.u = acc;
    float2 r = ((const float2*)g_r)[(size_t)wid * 32 + lane];
    float v0 = tanhf(a.f.x + r.x);
    float v1 = tanhf(a.f.y + r.y);
    float mx = fmaxf(v0, v1);
    #pragma unroll
    for (int o = 16; o > 0; o >>= 1) mx = fmaxf(mx, __shfl_xor_sync(0xffffffffu, mx, o));
    float e0 = expf(v0 - mx), e1 = expf(v1 - mx);
    float s = e0 + e1;
    #pragma unroll
    for (int o = 16; o > 0; o >>= 1) s += __shfl_xor_sync(0xffffffffu, s, o);
    float inv = 1.0f / s;
    ((float2*)g_S)[(size_t)wid * 32 + lane] = make_float2(e0 * inv, e1 * inv);
}

// ---------------------------------------------------------------- K4: out[b,k,c] = sum_n S[b,n,k] * x[b,n,c]  (f32x2)
// Grid (B, NPER/128). Reduces directly into d_out (pre-zeroed).
__global__ void k4_pool(const float* __restrict__ x, float* __restrict__ out) {
    extern __shared__ float sm4[];
    float* Ss = sm4;             // 128*64  = 32KB
    float* Xs = sm4 + 128 * KP;  // 128*128 = 64KB
    int b  = blockIdx.x;
    int n0 = blockIdx.y * 128;
    int t  = threadIdx.x;        // 256

    const float4* Sg = (const float4*)(g_S + ((size_t)b * NPER + n0) * KP);
    for (int i = t; i < 128 * KP / 4; i += 256) ((float4*)Ss)[i] = Sg[i];
    const float4* Xg = (const float4*)(x + ((size_t)b * NPER + n0) * CCH);
    for (int i = t; i < 128 * CCH / 4; i += 256) ((float4*)Xs)[i] = Xg[i];
    __syncthreads();

    int k0 = (t >> 4) * 4;       // 4 k rows
    int c0 = (t & 15) * 8;       // 8 c cols = 4 packed pairs
    ull acc[4][4];
    #pragma unroll
    for (int i = 0; i < 4; i++)
        #pragma unroll
        for (int j = 0; j < 4; j++) acc[i][j] = 0ull;

    #pragma unroll 4
    for (int n = 0; n < 128; n++) {
        float4 s4 = *(const float4*)&Ss[n * KP + k0];
        ull sd[4];
        PACK_DUP(sd[0], s4.x); PACK_DUP(sd[1], s4.y);
        PACK_DUP(sd[2], s4.z); PACK_DUP(sd[3], s4.w);
        ull xp[4];
        #pragma unroll
        for (int j = 0; j < 4; j++)
            xp[j] = *(const ull*)&Xs[n * CCH + c0 + 2 * j];
        #pragma unroll
        for (int i = 0; i < 4; i++)
            #pragma unroll
            for (int j = 0; j < 4; j++)
                FMA_F32X2(acc[i][j], sd[i], xp[j], acc[i][j]);
    }

    #pragma unroll
    for (int i = 0; i < 4; i++) {
        F2U a0, a1, a2, a3;
        a0.u = acc[i][0]; a1.u = acc[i][1]; a2.u = acc[i][2]; a3.u = acc[i][3];
        float* p = out + ((size_t)b * KP + k0 + i) * CCH + c0;
        asm volatile("red.global.add.v4.f32 [%0], {%1,%2,%3,%4};"
                     :: "l"(p), "f"(a0.f.x), "f"(a0.f.y), "f"(a1.f.x), "f"(a1.f.y) : "memory");
        asm volatile("red.global.add.v4.f32 [%0], {%1,%2,%3,%4};"
                     :: "l"(p + 4), "f"(a2.f.x), "f"(a2.f.y), "f"(a3.f.x), "f"(a3.f.y) : "memory");
    }
}

// ---------------------------------------------------------------- extras
__global__ void k_extras(float* __restrict__ out, int out_size) {
    int gid = blockIdx.x * blockDim.x + threadIdx.x;
    if (gid < N2 && out_size >= N1 + N2) {
        int r   = gid / (BB * KP * KP);
        int rem = gid - r * (BB * KP * KP);
        int b   = rem >> 12;       // / (K*K) = /4096
        int ij  = rem & 4095;
        int i   = ij >> 6, j = ij & 63;
        out[N1 + gid] = (float)(b * KP + (r == 0 ? i : j));
    }
    if (gid < N3 && out_size >= N1 + N2 + N3) {
        out[N1 + N2 + gid] = (float)(gid >> 6);   // batch_out[b*K+k] = b
    }
}

// ---------------------------------------------------------------- launch
extern "C" void kernel_launch(void* const* d_in, const int* in_sizes, int n_in,
                              void* d_out, int out_size) {
    const float* x  = (const float*)d_in[0];
    const int*   ei = (const int*)  d_in[1];
    // d_in[2] = batch (unused; equal-size graphs)
    const float* Wm = (const float*)d_in[3];
    const float* Wr = (const float*)d_in[4];
    const float* bv = (const float*)d_in[5];
    float* out = (float*)d_out;

    cudaFuncSetAttribute(k1_gemm, cudaFuncAttributeMaxDynamicSharedMemorySize, 131072);
    cudaFuncSetAttribute(k4_pool, cudaFuncAttributeMaxDynamicSharedMemorySize, 98304);

    k_init<<<288, 512>>>(out);
    k1_gemm<<<NN / 128, 512, 131072>>>(x, Wm, Wr, bv);
    k_count<<<256, 512>>>(ei);
    k_scan<<<BB, NPER>>>();
    k_fill<<<EE / 256, 256>>>(ei);
    k_spmm<<<NN / 8, 256>>>();
    k4_pool<<<dim3(BB, NPER / 128), 256, 98304>>>(x, out);
    if (out_size >= N1 + N2) k_extras<<<(N2 + 255) / 256, 256>>>(out, out_size);
}